// round 14
// baseline (speedup 1.0000x reference)
#include <cuda_runtime.h>
#include <cuda_fp16.h>

// ===========================================================================
// GCN: 3 layers, pull-based padded-CSR aggregation, no float atomics.
//   out_i = leakyrelu( dinv_i * ( sum_{e: dst=i} g[src_e] + g[i] ) + b )
//   with g = fp16( (h @ W) * dinv )  (row-scaled in GEMM epilogue)
//
// R2: multi-block scan. R4: fp16 gather table. R5: padded 4/8-edge agg.
// R6: HMMA GEMM. R10: agg64 2-edge unroll. R12: fp16 GEMM input (null).
// R13: W transpose/convert hoisted out of hgemm into k_part (one-time
//      g_Wt[3]); hgemm W staging = coalesced uint4 memcpy. Kills the
//      8-way-conflicted STS.16 prologue repeated by all 782 blocks.
// ===========================================================================

#define NMAX 100000
#define EMAX 1600000
#define PADMAX (EMAX + 8 * NMAX)
#define SCAN_TILE 1024
#define NBLK ((NMAX + SCAN_TILE - 1) / SCAN_TILE)   // 98
#define WS 72   // padded stride of transposed W (halves)

__device__ int    g_deg[NMAX];                   // .bss zero; re-zeroed by k_offs
__device__ float  g_dinv[NMAX];
__device__ int    g_offs[NMAX + 1];              // padded CSR offsets
__device__ int    g_cur[NMAX];
__device__ int    g_csrc[PADMAX];
__device__ int    g_bsum[NBLK];
__device__ __align__(16) __half g_Gh[(size_t)(NMAX + 1) * 64]; // gather table (+ zero row)
__device__ __align__(16) __half g_Hh[(size_t)NMAX * 64];       // fp16 layer input
__device__ __align__(16) __half g_Wt[3][64 * WS];              // fp16 transposed weights

// per-warp dtype probe: int64 entries < 2^31 have zero high words; for int32
// data those words are random node ids -> 16 zeros is impossible.
__device__ __forceinline__ int probe_is64(const unsigned* w, int lane) {
    unsigned hw = w[2 * (lane & 15) + 1];
    return __ballot_sync(0xffffffffu, hw == 0u) == 0xffffffffu;
}

// ---------------------------------------------------------------- CSR build
// Fused: degree count (2 edges/thread) + x fp32->fp16 convert (8 vals/thread).
__global__ void k_count(const void* __restrict__ ei, const float* __restrict__ x,
                        int E, int N) {
    int lane = threadIdx.x & 31;
    int is64 = probe_is64((const unsigned*)ei, lane);
    int t = blockIdx.x * blockDim.x + threadIdx.x;

    // convert slice of x -> g_Hh
    int nv = N * 8;                 // uint4 granules of fp16 output
    if (t < nv) {
        const float4* xf = (const float4*)x;
        float4 a = xf[(size_t)t * 2];
        float4 b = xf[(size_t)t * 2 + 1];
        __half2 h[4] = { __floats2half2_rn(a.x, a.y), __floats2half2_rn(a.z, a.w),
                         __floats2half2_rn(b.x, b.y), __floats2half2_rn(b.z, b.w) };
        *(uint4*)&g_Hh[(size_t)t * 8] = *(const uint4*)h;
    }

    int e0 = t * 2;
    if (e0 >= E) return;
    int d0, d1;
    if (is64) {
        longlong2 v = ((const longlong2*)ei)[((size_t)E + e0) >> 1];
        d0 = (int)v.x; d1 = (int)v.y;
    } else {
        int2 v = ((const int2*)ei)[((size_t)E + e0) >> 1];
        d0 = v.x; d1 = v.y;
    }
    if ((unsigned)d0 < (unsigned)N) atomicAdd(&g_deg[d0], 1);
    if (e0 + 1 < E && (unsigned)d1 < (unsigned)N) atomicAdd(&g_deg[d1], 1);
}

// per-block sums of PADDED degrees; also one-time W transpose/convert.
__global__ void k_part(int N, const float* __restrict__ W1,
                       const float* __restrict__ W2, const float* __restrict__ W3) {
    int t = blockIdx.x * SCAN_TILE + threadIdx.x;
    // W convert: layers sized 4096/4096/2048 fp32 elements
    if (t < 2 * 4096 + 2048) {
        const float* W;
        int layer, idx, dout;
        if (t < 4096)       { layer = 0; idx = t;        W = W1; dout = 64; }
        else if (t < 8192)  { layer = 1; idx = t - 4096; W = W2; dout = 64; }
        else                { layer = 2; idx = t - 8192; W = W3; dout = 32; }
        int k = idx / dout, n = idx % dout;
        g_Wt[layer][n * WS + k] = __float2half_rn(W[idx]);
    }

    int i = t;
    int d  = (i < N) ? g_deg[i] : 0;
    int pd = (d + 7) & ~7;
    int lane = threadIdx.x & 31, wid = threadIdx.x >> 5;
    #pragma unroll
    for (int o = 16; o > 0; o >>= 1) pd += __shfl_down_sync(0xffffffffu, pd, o);
    __shared__ int ws[32];
    if (lane == 0) ws[wid] = pd;
    __syncthreads();
    if (wid == 0) {
        int v = ws[lane];
        #pragma unroll
        for (int o = 16; o > 0; o >>= 1) v += __shfl_down_sync(0xffffffffu, v, o);
        if (lane == 0) g_bsum[blockIdx.x] = v;
    }
}

// fused: scan of block sums + block-wide scan of padded degrees ->
// offs/cur/dinv, sentinel pad fill, and re-zero g_deg for the next call.
__global__ void k_offs(int N) {
    __shared__ int sb[128];
    __shared__ int ws[32];
    int t = threadIdx.x;

    if (t < 128) {
        int v = (t < NBLK) ? g_bsum[t] : 0;
        int lane = t & 31, w = t >> 5;
        int s = v;
        #pragma unroll
        for (int o = 1; o < 32; o <<= 1) {
            int u = __shfl_up_sync(0xffffffffu, s, o);
            if (lane >= o) s += u;
        }
        if (lane == 31) ws[w] = s;
        sb[t] = s;
    }
    __syncthreads();
    if (t < 128) {
        int w = t >> 5;
        int add = 0;
        for (int q = 0; q < w; q++) add += ws[q];
        sb[t] += add;
    }
    __syncthreads();
    int blockpre = (blockIdx.x == 0) ? 0 : sb[blockIdx.x - 1];
    __syncthreads();  // ws reused below

    int i = blockIdx.x * SCAN_TILE + t;
    int d  = (i < N) ? g_deg[i] : 0;
    int pd = (d + 7) & ~7;
    int lane = t & 31, wid = t >> 5;
    int v = pd;
    #pragma unroll
    for (int o = 1; o < 32; o <<= 1) {
        int u = __shfl_up_sync(0xffffffffu, v, o);
        if (lane >= o) v += u;
    }
    if (lane == 31) ws[wid] = v;
    __syncthreads();
    if (wid == 0) {
        int w = ws[lane];
        #pragma unroll
        for (int o = 1; o < 32; o <<= 1) {
            int u = __shfl_up_sync(0xffffffffu, w, o);
            if (lane >= o) w += u;
        }
        ws[lane] = w;
    }
    __syncthreads();
    int incl = v + ((wid > 0) ? ws[wid - 1] : 0);
    int excl = incl - pd + blockpre;
    if (i < N) {
        g_offs[i] = excl;
        g_cur[i]  = excl;
        g_dinv[i] = rsqrtf((float)(d + 1));     // +1 self loop (real degree)
        for (int p = excl + d; p < excl + pd; p++) g_csrc[p] = NMAX;  // sentinel
        g_deg[i] = 0;                            // ready for next replay
        if (i == N - 1) g_offs[N] = excl + pd;
    }
}

__global__ void k_fill(const void* __restrict__ ei, int E, int N) {
    int lane = threadIdx.x & 31;
    int is64 = probe_is64((const unsigned*)ei, lane);
    int t = blockIdx.x * blockDim.x + threadIdx.x;
    int e0 = t * 2;
    if (e0 >= E) return;
    int s0, s1, d0, d1;
    if (is64) {
        longlong2 sv = ((const longlong2*)ei)[(size_t)e0 >> 1];
        longlong2 dv = ((const longlong2*)ei)[((size_t)E + e0) >> 1];
        s0 = (int)sv.x; s1 = (int)sv.y;
        d0 = (int)dv.x; d1 = (int)dv.y;
    } else {
        int2 sv = ((const int2*)ei)[(size_t)e0 >> 1];
        int2 dv = ((const int2*)ei)[((size_t)E + e0) >> 1];
        s0 = sv.x; s1 = sv.y;
        d0 = dv.x; d1 = dv.y;
    }
    if ((unsigned)d0 < (unsigned)N) {
        int pos = atomicAdd(&g_cur[d0], 1);
        g_csrc[pos] = ((unsigned)s0 < (unsigned)N) ? s0 : 0;
    }
    if (e0 + 1 < E && (unsigned)d1 < (unsigned)N) {
        int pos = atomicAdd(&g_cur[d1], 1);
        g_csrc[pos] = ((unsigned)s1 < (unsigned)N) ? s1 : 0;
    }
}

// ---------------------------------------------------------------- HMMA GEMM
__device__ __forceinline__ void mma16816(float c[4], unsigned a0, unsigned a1,
                                         unsigned a2, unsigned a3,
                                         unsigned b0, unsigned b1) {
    asm volatile(
        "mma.sync.aligned.m16n8k16.row.col.f32.f16.f16.f32 "
        "{%0,%1,%2,%3}, {%4,%5,%6,%7}, {%8,%9}, {%0,%1,%2,%3};"
        : "+f"(c[0]), "+f"(c[1]), "+f"(c[2]), "+f"(c[3])
        : "r"(a0), "r"(a1), "r"(a2), "r"(a3), "r"(b0), "r"(b1));
}

__device__ __forceinline__ void ldsm_x4(unsigned& r0, unsigned& r1,
                                        unsigned& r2, unsigned& r3,
                                        unsigned addr) {
    asm volatile(
        "ldmatrix.sync.aligned.m8n8.x4.shared.b16 {%0,%1,%2,%3}, [%4];"
        : "=r"(r0), "=r"(r1), "=r"(r2), "=r"(r3) : "r"(addr));
}

// g_Gh = fp16( (g_Hh @ W) * dinv[row] ).  W from precomputed g_Wt (fp16,
// transposed, padded). 256 threads / 8 warps, tile 128 rows x DOUT, K=64.
// All staging is raw uint4 copies; ldmatrix phases conflict-free.
template <int DOUT>
__global__ void k_hgemm(int layer, int N) {
    constexpr int S = WS;
    __shared__ __align__(16) __half sX[128 * S];
    __shared__ __align__(16) __half sWt[DOUT * S];   // transposed: sWt[n][k]

    int tid = threadIdx.x, lane = tid & 31, w = tid >> 5;
    int rowBase = blockIdx.x * 128;

    // W staging: coalesced uint4 memcpy of precomputed transposed fp16 W
    {
        const uint4* src = (const uint4*)g_Wt[layer];
        uint4* dst = (uint4*)sWt;
        #pragma unroll
        for (int i = tid; i < DOUT * (S / 8); i += 256) dst[i] = src[i];
    }
    // X tile: 4 x (LDG.128 + STS.128) per thread
    const uint4* Hv = (const uint4*)g_Hh;
    #pragma unroll
    for (int i = 0; i < 4; i++) {
        int idx = tid + i * 256;            // uint4 index within 128x8
        int r = idx >> 3, c8 = idx & 7;
        int grow = rowBase + r;
        uint4 v = (grow < N) ? Hv[(size_t)grow * 8 + c8]
                             : make_uint4(0u, 0u, 0u, 0u);
        *(uint4*)&sX[r * S + c8 * 8] = v;
    }
    __syncthreads();

    constexpr int NT = DOUT / 8;
    float acc[NT][4];
    #pragma unroll
    for (int nt = 0; nt < NT; nt++)
        #pragma unroll
        for (int q = 0; q < 4; q++) acc[nt][q] = 0.f;

    unsigned xs  = (unsigned)__cvta_generic_to_shared(sX);
    unsigned wsb = (unsigned)__cvta_generic_to_shared(sWt);
    int arow  = w * 16 + (lane & 15);
    int acol8 = (lane >> 4) * 8;
    int bn  = ((lane >> 4) << 3) | (lane & 7);
    int bk8 = ((lane >> 3) & 1) << 3;

    #pragma unroll
    for (int kt = 0; kt < 4; kt++) {
        int k0 = kt * 16;
        unsigned a0, a1, a2, a3;
        ldsm_x4(a0, a1, a2, a3, xs + (arow * S + k0 + acol8) * 2);
        #pragma unroll
        for (int nt2 = 0; nt2 < NT / 2; nt2++) {
            unsigned b00, b01, b10, b11;
            ldsm_x4(b00, b01, b10, b11,
                    wsb + ((nt2 * 16 + bn) * S + k0 + bk8) * 2);
            mma16816(acc[nt2 * 2],     a0, a1, a2, a3, b00, b01);
            mma16816(acc[nt2 * 2 + 1], a0, a1, a2, a3, b10, b11);
        }
    }

    // epilogue: scale by dinv, convert, store half2
    int g = lane >> 2, tg = lane & 3;
    int gr0 = rowBase + w * 16 + g, gr1 = gr0 + 8;
    bool ok0 = gr0 < N, ok1 = gr1 < N;
    float s0 = ok0 ? g_dinv[gr0] : 0.f;
    float s1 = ok1 ? g_dinv[gr1] : 0.f;
    __half2* Gh2 = (__half2*)g_Gh;
    #pragma unroll
    for (int nt = 0; nt < NT; nt++) {
        int col = nt * 8 + tg * 2;
        if (ok0)
            Gh2[((size_t)gr0 * DOUT + col) >> 1] =
                __floats2half2_rn(acc[nt][0] * s0, acc[nt][1] * s0);
        if (ok1)
            Gh2[((size_t)gr1 * DOUT + col) >> 1] =
                __floats2half2_rn(acc[nt][2] * s1, acc[nt][3] * s1);
    }
}

// ---------------------------------------------------------------- aggregate
// D=64: warp-per-node, 8 edges/iter, fp16 pair-add then fp32 accumulate.
// Also emits the fp16 copy of the layer output (next GEMM's input).
template <bool RELU>
__global__ void k_agg64(const float* __restrict__ bias, float* __restrict__ out, int N) {
    int gid  = blockIdx.x * blockDim.x + threadIdx.x;
    int node = gid >> 5;
    int lane = gid & 31;
    if (node >= N) return;

    const uint4* __restrict__ G4 = (const uint4*)g_Gh;  // row = 8 granules
    int sub = lane & 7;
    int grp = lane >> 3;
    int beg = g_offs[node];
    int end = g_offs[node + 1];

    float acc[8];
    #pragma unroll
    for (int k = 0; k < 8; k++) acc[k] = 0.f;

    for (int e0 = beg; e0 < end; e0 += 32) {
        int idx = e0 + lane;
        int sl  = (idx < end) ? g_csrc[idx] : NMAX;
        int cnt = min(32, end - e0);          // multiple of 8
        for (int j = 0; j < cnt; j += 8) {
            int s1 = __shfl_sync(0xffffffffu, sl, j + grp);
            int s2 = __shfl_sync(0xffffffffu, sl, j + 4 + grp);
            uint4 v1 = G4[(size_t)s1 * 8 + sub];
            uint4 v2 = G4[(size_t)s2 * 8 + sub];
            const __half2* h1 = (const __half2*)&v1;
            const __half2* h2 = (const __half2*)&v2;
            #pragma unroll
            for (int q = 0; q < 4; q++) {
                float2 f = __half22float2(__hadd2(h1[q], h2[q]));
                acc[2 * q]     += f.x;
                acc[2 * q + 1] += f.y;
            }
        }
    }
    #pragma unroll
    for (int k = 0; k < 8; k++) {
        acc[k] += __shfl_xor_sync(0xffffffffu, acc[k], 8);
        acc[k] += __shfl_xor_sync(0xffffffffu, acc[k], 16);
    }
    {
        uint4 v = G4[(size_t)node * 8 + sub];
        const __half2* h = (const __half2*)&v;
        #pragma unroll
        for (int q = 0; q < 4; q++) {
            float2 f = __half22float2(h[q]);
            acc[2 * q]     += f.x;
            acc[2 * q + 1] += f.y;
        }
    }
    if (lane < 8) {
        float sc = g_dinv[node];
        float o[8];
        #pragma unroll
        for (int k = 0; k < 8; k++) {
            o[k] = acc[k] * sc + bias[lane * 8 + k];
            if (RELU) o[k] = (o[k] >= 0.f) ? o[k] : 0.01f * o[k];
        }
        float* dst = out + (size_t)node * 64 + lane * 8;
        *(float4*)(dst)     = make_float4(o[0], o[1], o[2], o[3]);
        *(float4*)(dst + 4) = make_float4(o[4], o[5], o[6], o[7]);
        // fp16 copy for the next GEMM
        __half2 hh[4] = { __floats2half2_rn(o[0], o[1]), __floats2half2_rn(o[2], o[3]),
                          __floats2half2_rn(o[4], o[5]), __floats2half2_rn(o[6], o[7]) };
        *(uint4*)&g_Hh[(size_t)node * 64 + lane * 8] = *(const uint4*)hh;
    }
}

// D=32: warp-per-node, 8 edges/iter. Sentinel remapped to the zero tail row.
template <bool RELU>
__global__ void k_agg32(const float* __restrict__ bias, float* __restrict__ out, int N) {
    int gid  = blockIdx.x * blockDim.x + threadIdx.x;
    int node = gid >> 5;
    int lane = gid & 31;
    if (node >= N) return;

    const uint4* __restrict__ G4 = (const uint4*)g_Gh;  // row = 4 granules
    int sub = lane & 3;
    int grp = lane >> 2;
    int beg = g_offs[node];
    int end = g_offs[node + 1];

    float acc[8];
    #pragma unroll
    for (int k = 0; k < 8; k++) acc[k] = 0.f;

    for (int e0 = beg; e0 < end; e0 += 32) {
        int idx = e0 + lane;
        int sl  = (idx < end) ? g_csrc[idx] : NMAX;
        int cnt = min(32, end - e0);          // multiple of 8
        for (int j = 0; j < cnt; j += 8) {
            int s = __shfl_sync(0xffffffffu, sl, j + grp);
            size_t rb = (s == NMAX) ? ((size_t)NMAX * 8) : ((size_t)s * 4);
            uint4 v = G4[rb + sub];
            const __half2* h = (const __half2*)&v;
            #pragma unroll
            for (int q = 0; q < 4; q++) {
                float2 f = __half22float2(h[q]);
                acc[2 * q]     += f.x;
                acc[2 * q + 1] += f.y;
            }
        }
    }
    #pragma unroll
    for (int k = 0; k < 8; k++) {
        acc[k] += __shfl_xor_sync(0xffffffffu, acc[k], 4);
        acc[k] += __shfl_xor_sync(0xffffffffu, acc[k], 8);
        acc[k] += __shfl_xor_sync(0xffffffffu, acc[k], 16);
    }
    {
        uint4 v = G4[(size_t)node * 4 + sub];
        const __half2* h = (const __half2*)&v;
        #pragma unroll
        for (int q = 0; q < 4; q++) {
            float2 f = __half22float2(h[q]);
            acc[2 * q]     += f.x;
            acc[2 * q + 1] += f.y;
        }
    }
    if (lane < 4) {
        float sc = g_dinv[node];
        float o[8];
        #pragma unroll
        for (int k = 0; k < 8; k++) {
            o[k] = acc[k] * sc + bias[lane * 8 + k];
            if (RELU) o[k] = (o[k] >= 0.f) ? o[k] : 0.01f * o[k];
        }
        float* dst = out + (size_t)node * 32 + lane * 8;
        *(float4*)(dst)     = make_float4(o[0], o[1], o[2], o[3]);
        *(float4*)(dst + 4) = make_float4(o[4], o[5], o[6], o[7]);
    }
}

// ---------------------------------------------------------------- launch
extern "C" void kernel_launch(void* const* d_in, const int* in_sizes, int n_in,
                              void* d_out, int out_size) {
    const float* x  = (const float*)d_in[0];
    const void*  ei = d_in[1];
    const float* W1 = (const float*)d_in[2];
    const float* b1 = (const float*)d_in[3];
    const float* W2 = (const float*)d_in[4];
    const float* b2 = (const float*)d_in[5];
    const float* W3 = (const float*)d_in[6];
    const float* b3 = (const float*)d_in[7];
    float* out = (float*)d_out;

    int N = in_sizes[0] / 64;
    int E = in_sizes[1] / 2;

    float* emb1 = out;
    float* emb2 = out + (size_t)N * 64;
    float* emb3 = out + (size_t)N * 128;

    int nblk = (N + SCAN_TILE - 1) / SCAN_TILE;
    int gemm_blocks = (N + 127) / 128;
    int agg_blocks = (N * 32 + 255) / 256;
    int cnt_threads = (E + 1) / 2 > N * 8 ? (E + 1) / 2 : N * 8;
    int cnt_blocks = (cnt_threads + 255) / 256;
    int edge_blocks = ((E + 1) / 2 + 255) / 256;

    // (1) fused convert + degree count
    k_count<<<cnt_blocks, 256>>>(ei, x, E, N);
    // (2) block sums + one-time W transpose/convert
    k_part<<<nblk, SCAN_TILE>>>(N, W1, W2, W3);
    k_offs<<<nblk, SCAN_TILE>>>(N);
    // (4) gemm1 — ncu capture slot: verify hoisted-W theory
    k_hgemm<64><<<gemm_blocks, 256>>>(0, N);
    k_fill<<<edge_blocks, 256>>>(ei, E, N);
    k_agg64<true><<<agg_blocks, 256>>>(b1, emb1, N);
    k_hgemm<64><<<gemm_blocks, 256>>>(1, N);
    k_agg64<true><<<agg_blocks, 256>>>(b2, emb2, N);
    k_hgemm<32><<<gemm_blocks, 256>>>(2, N);
    k_agg32<false><<<agg_blocks, 256>>>(b3, emb3, N);
}

// round 15
// speedup vs baseline: 1.0006x; 1.0006x over previous
#include <cuda_runtime.h>
#include <cuda_fp16.h>

// ===========================================================================
// GCN: 3 layers, pull-based padded-CSR aggregation, no float atomics.
//   out_i = leakyrelu( dinv_i * ( sum_{e: dst=i} g[src_e] + g[i] ) + b )
//   with g = fp16( (h @ W) * dinv )  (row-scaled in GEMM epilogue)
//
// R2: multi-block scan. R4: fp16 gather table. R5: padded 4/8-edge agg.
// R6: HMMA GEMM. R10: agg64 2-edge unroll. R12: fp16 GEMM input (null).
// R13: W transpose/convert hoisted out of hgemm into k_part (one-time
//      g_Wt[3]); hgemm W staging = coalesced uint4 memcpy. Kills the
//      8-way-conflicted STS.16 prologue repeated by all 782 blocks.
// ===========================================================================

#define NMAX 100000
#define EMAX 1600000
#define PADMAX (EMAX + 8 * NMAX)
#define SCAN_TILE 1024
#define NBLK ((NMAX + SCAN_TILE - 1) / SCAN_TILE)   // 98
#define WS 72   // padded stride of transposed W (halves)

__device__ int    g_deg[NMAX];                   // .bss zero; re-zeroed by k_offs
__device__ float  g_dinv[NMAX];
__device__ int    g_offs[NMAX + 1];              // padded CSR offsets
__device__ int    g_cur[NMAX];
__device__ int    g_csrc[PADMAX];
__device__ int    g_bsum[NBLK];
__device__ __align__(16) __half g_Gh[(size_t)(NMAX + 1) * 64]; // gather table (+ zero row)
__device__ __align__(16) __half g_Hh[(size_t)NMAX * 64];       // fp16 layer input
__device__ __align__(16) __half g_Wt[3][64 * WS];              // fp16 transposed weights

// per-warp dtype probe: int64 entries < 2^31 have zero high words; for int32
// data those words are random node ids -> 16 zeros is impossible.
__device__ __forceinline__ int probe_is64(const unsigned* w, int lane) {
    unsigned hw = w[2 * (lane & 15) + 1];
    return __ballot_sync(0xffffffffu, hw == 0u) == 0xffffffffu;
}

// ---------------------------------------------------------------- CSR build
// Fused: degree count (2 edges/thread) + x fp32->fp16 convert (8 vals/thread).
__global__ void k_count(const void* __restrict__ ei, const float* __restrict__ x,
                        int E, int N) {
    int lane = threadIdx.x & 31;
    int is64 = probe_is64((const unsigned*)ei, lane);
    int t = blockIdx.x * blockDim.x + threadIdx.x;

    // convert slice of x -> g_Hh
    int nv = N * 8;                 // uint4 granules of fp16 output
    if (t < nv) {
        const float4* xf = (const float4*)x;
        float4 a = xf[(size_t)t * 2];
        float4 b = xf[(size_t)t * 2 + 1];
        __half2 h[4] = { __floats2half2_rn(a.x, a.y), __floats2half2_rn(a.z, a.w),
                         __floats2half2_rn(b.x, b.y), __floats2half2_rn(b.z, b.w) };
        *(uint4*)&g_Hh[(size_t)t * 8] = *(const uint4*)h;
    }

    int e0 = t * 2;
    if (e0 >= E) return;
    int d0, d1;
    if (is64) {
        longlong2 v = ((const longlong2*)ei)[((size_t)E + e0) >> 1];
        d0 = (int)v.x; d1 = (int)v.y;
    } else {
        int2 v = ((const int2*)ei)[((size_t)E + e0) >> 1];
        d0 = v.x; d1 = v.y;
    }
    if ((unsigned)d0 < (unsigned)N) atomicAdd(&g_deg[d0], 1);
    if (e0 + 1 < E && (unsigned)d1 < (unsigned)N) atomicAdd(&g_deg[d1], 1);
}

// per-block sums of PADDED degrees; also one-time W transpose/convert.
__global__ void k_part(int N, const float* __restrict__ W1,
                       const float* __restrict__ W2, const float* __restrict__ W3) {
    int t = blockIdx.x * SCAN_TILE + threadIdx.x;
    // W convert: layers sized 4096/4096/2048 fp32 elements
    if (t < 2 * 4096 + 2048) {
        const float* W;
        int layer, idx, dout;
        if (t < 4096)       { layer = 0; idx = t;        W = W1; dout = 64; }
        else if (t < 8192)  { layer = 1; idx = t - 4096; W = W2; dout = 64; }
        else                { layer = 2; idx = t - 8192; W = W3; dout = 32; }
        int k = idx / dout, n = idx % dout;
        g_Wt[layer][n * WS + k] = __float2half_rn(W[idx]);
    }

    int i = t;
    int d  = (i < N) ? g_deg[i] : 0;
    int pd = (d + 7) & ~7;
    int lane = threadIdx.x & 31, wid = threadIdx.x >> 5;
    #pragma unroll
    for (int o = 16; o > 0; o >>= 1) pd += __shfl_down_sync(0xffffffffu, pd, o);
    __shared__ int ws[32];
    if (lane == 0) ws[wid] = pd;
    __syncthreads();
    if (wid == 0) {
        int v = ws[lane];
        #pragma unroll
        for (int o = 16; o > 0; o >>= 1) v += __shfl_down_sync(0xffffffffu, v, o);
        if (lane == 0) g_bsum[blockIdx.x] = v;
    }
}

// fused: scan of block sums + block-wide scan of padded degrees ->
// offs/cur/dinv, sentinel pad fill, and re-zero g_deg for the next call.
__global__ void k_offs(int N) {
    __shared__ int sb[128];
    __shared__ int ws[32];
    int t = threadIdx.x;

    if (t < 128) {
        int v = (t < NBLK) ? g_bsum[t] : 0;
        int lane = t & 31, w = t >> 5;
        int s = v;
        #pragma unroll
        for (int o = 1; o < 32; o <<= 1) {
            int u = __shfl_up_sync(0xffffffffu, s, o);
            if (lane >= o) s += u;
        }
        if (lane == 31) ws[w] = s;
        sb[t] = s;
    }
    __syncthreads();
    if (t < 128) {
        int w = t >> 5;
        int add = 0;
        for (int q = 0; q < w; q++) add += ws[q];
        sb[t] += add;
    }
    __syncthreads();
    int blockpre = (blockIdx.x == 0) ? 0 : sb[blockIdx.x - 1];
    __syncthreads();  // ws reused below

    int i = blockIdx.x * SCAN_TILE + t;
    int d  = (i < N) ? g_deg[i] : 0;
    int pd = (d + 7) & ~7;
    int lane = t & 31, wid = t >> 5;
    int v = pd;
    #pragma unroll
    for (int o = 1; o < 32; o <<= 1) {
        int u = __shfl_up_sync(0xffffffffu, v, o);
        if (lane >= o) v += u;
    }
    if (lane == 31) ws[wid] = v;
    __syncthreads();
    if (wid == 0) {
        int w = ws[lane];
        #pragma unroll
        for (int o = 1; o < 32; o <<= 1) {
            int u = __shfl_up_sync(0xffffffffu, w, o);
            if (lane >= o) w += u;
        }
        ws[lane] = w;
    }
    __syncthreads();
    int incl = v + ((wid > 0) ? ws[wid - 1] : 0);
    int excl = incl - pd + blockpre;
    if (i < N) {
        g_offs[i] = excl;
        g_cur[i]  = excl;
        g_dinv[i] = rsqrtf((float)(d + 1));     // +1 self loop (real degree)
        for (int p = excl + d; p < excl + pd; p++) g_csrc[p] = NMAX;  // sentinel
        g_deg[i] = 0;                            // ready for next replay
        if (i == N - 1) g_offs[N] = excl + pd;
    }
}

__global__ void k_fill(const void* __restrict__ ei, int E, int N) {
    int lane = threadIdx.x & 31;
    int is64 = probe_is64((const unsigned*)ei, lane);
    int t = blockIdx.x * blockDim.x + threadIdx.x;
    int e0 = t * 2;
    if (e0 >= E) return;
    int s0, s1, d0, d1;
    if (is64) {
        longlong2 sv = ((const longlong2*)ei)[(size_t)e0 >> 1];
        longlong2 dv = ((const longlong2*)ei)[((size_t)E + e0) >> 1];
        s0 = (int)sv.x; s1 = (int)sv.y;
        d0 = (int)dv.x; d1 = (int)dv.y;
    } else {
        int2 sv = ((const int2*)ei)[(size_t)e0 >> 1];
        int2 dv = ((const int2*)ei)[((size_t)E + e0) >> 1];
        s0 = sv.x; s1 = sv.y;
        d0 = dv.x; d1 = dv.y;
    }
    if ((unsigned)d0 < (unsigned)N) {
        int pos = atomicAdd(&g_cur[d0], 1);
        g_csrc[pos] = ((unsigned)s0 < (unsigned)N) ? s0 : 0;
    }
    if (e0 + 1 < E && (unsigned)d1 < (unsigned)N) {
        int pos = atomicAdd(&g_cur[d1], 1);
        g_csrc[pos] = ((unsigned)s1 < (unsigned)N) ? s1 : 0;
    }
}

// ---------------------------------------------------------------- HMMA GEMM
__device__ __forceinline__ void mma16816(float c[4], unsigned a0, unsigned a1,
                                         unsigned a2, unsigned a3,
                                         unsigned b0, unsigned b1) {
    asm volatile(
        "mma.sync.aligned.m16n8k16.row.col.f32.f16.f16.f32 "
        "{%0,%1,%2,%3}, {%4,%5,%6,%7}, {%8,%9}, {%0,%1,%2,%3};"
        : "+f"(c[0]), "+f"(c[1]), "+f"(c[2]), "+f"(c[3])
        : "r"(a0), "r"(a1), "r"(a2), "r"(a3), "r"(b0), "r"(b1));
}

__device__ __forceinline__ void ldsm_x4(unsigned& r0, unsigned& r1,
                                        unsigned& r2, unsigned& r3,
                                        unsigned addr) {
    asm volatile(
        "ldmatrix.sync.aligned.m8n8.x4.shared.b16 {%0,%1,%2,%3}, [%4];"
        : "=r"(r0), "=r"(r1), "=r"(r2), "=r"(r3) : "r"(addr));
}

// g_Gh = fp16( (g_Hh @ W) * dinv[row] ).  W from precomputed g_Wt (fp16,
// transposed, padded). 256 threads / 8 warps, tile 128 rows x DOUT, K=64.
// All staging is raw uint4 copies; ldmatrix phases conflict-free.
template <int DOUT>
__global__ void k_hgemm(int layer, int N) {
    constexpr int S = WS;
    __shared__ __align__(16) __half sX[128 * S];
    __shared__ __align__(16) __half sWt[DOUT * S];   // transposed: sWt[n][k]

    int tid = threadIdx.x, lane = tid & 31, w = tid >> 5;
    int rowBase = blockIdx.x * 128;

    // W staging: coalesced uint4 memcpy of precomputed transposed fp16 W
    {
        const uint4* src = (const uint4*)g_Wt[layer];
        uint4* dst = (uint4*)sWt;
        #pragma unroll
        for (int i = tid; i < DOUT * (S / 8); i += 256) dst[i] = src[i];
    }
    // X tile: 4 x (LDG.128 + STS.128) per thread
    const uint4* Hv = (const uint4*)g_Hh;
    #pragma unroll
    for (int i = 0; i < 4; i++) {
        int idx = tid + i * 256;            // uint4 index within 128x8
        int r = idx >> 3, c8 = idx & 7;
        int grow = rowBase + r;
        uint4 v = (grow < N) ? Hv[(size_t)grow * 8 + c8]
                             : make_uint4(0u, 0u, 0u, 0u);
        *(uint4*)&sX[r * S + c8 * 8] = v;
    }
    __syncthreads();

    constexpr int NT = DOUT / 8;
    float acc[NT][4];
    #pragma unroll
    for (int nt = 0; nt < NT; nt++)
        #pragma unroll
        for (int q = 0; q < 4; q++) acc[nt][q] = 0.f;

    unsigned xs  = (unsigned)__cvta_generic_to_shared(sX);
    unsigned wsb = (unsigned)__cvta_generic_to_shared(sWt);
    int arow  = w * 16 + (lane & 15);
    int acol8 = (lane >> 4) * 8;
    int bn  = ((lane >> 4) << 3) | (lane & 7);
    int bk8 = ((lane >> 3) & 1) << 3;

    #pragma unroll
    for (int kt = 0; kt < 4; kt++) {
        int k0 = kt * 16;
        unsigned a0, a1, a2, a3;
        ldsm_x4(a0, a1, a2, a3, xs + (arow * S + k0 + acol8) * 2);
        #pragma unroll
        for (int nt2 = 0; nt2 < NT / 2; nt2++) {
            unsigned b00, b01, b10, b11;
            ldsm_x4(b00, b01, b10, b11,
                    wsb + ((nt2 * 16 + bn) * S + k0 + bk8) * 2);
            mma16816(acc[nt2 * 2],     a0, a1, a2, a3, b00, b01);
            mma16816(acc[nt2 * 2 + 1], a0, a1, a2, a3, b10, b11);
        }
    }

    // epilogue: scale by dinv, convert, store half2
    int g = lane >> 2, tg = lane & 3;
    int gr0 = rowBase + w * 16 + g, gr1 = gr0 + 8;
    bool ok0 = gr0 < N, ok1 = gr1 < N;
    float s0 = ok0 ? g_dinv[gr0] : 0.f;
    float s1 = ok1 ? g_dinv[gr1] : 0.f;
    __half2* Gh2 = (__half2*)g_Gh;
    #pragma unroll
    for (int nt = 0; nt < NT; nt++) {
        int col = nt * 8 + tg * 2;
        if (ok0)
            Gh2[((size_t)gr0 * DOUT + col) >> 1] =
                __floats2half2_rn(acc[nt][0] * s0, acc[nt][1] * s0);
        if (ok1)
            Gh2[((size_t)gr1 * DOUT + col) >> 1] =
                __floats2half2_rn(acc[nt][2] * s1, acc[nt][3] * s1);
    }
}

// ---------------------------------------------------------------- aggregate
// D=64: warp-per-node, 8 edges/iter, fp16 pair-add then fp32 accumulate.
// Also emits the fp16 copy of the layer output (next GEMM's input).
template <bool RELU>
__global__ void k_agg64(const float* __restrict__ bias, float* __restrict__ out, int N) {
    int gid  = blockIdx.x * blockDim.x + threadIdx.x;
    int node = gid >> 5;
    int lane = gid & 31;
    if (node >= N) return;

    const uint4* __restrict__ G4 = (const uint4*)g_Gh;  // row = 8 granules
    int sub = lane & 7;
    int grp = lane >> 3;
    int beg = g_offs[node];
    int end = g_offs[node + 1];

    float acc[8];
    #pragma unroll
    for (int k = 0; k < 8; k++) acc[k] = 0.f;

    for (int e0 = beg; e0 < end; e0 += 32) {
        int idx = e0 + lane;
        int sl  = (idx < end) ? g_csrc[idx] : NMAX;
        int cnt = min(32, end - e0);          // multiple of 8
        for (int j = 0; j < cnt; j += 8) {
            int s1 = __shfl_sync(0xffffffffu, sl, j + grp);
            int s2 = __shfl_sync(0xffffffffu, sl, j + 4 + grp);
            uint4 v1 = G4[(size_t)s1 * 8 + sub];
            uint4 v2 = G4[(size_t)s2 * 8 + sub];
            const __half2* h1 = (const __half2*)&v1;
            const __half2* h2 = (const __half2*)&v2;
            #pragma unroll
            for (int q = 0; q < 4; q++) {
                float2 f = __half22float2(__hadd2(h1[q], h2[q]));
                acc[2 * q]     += f.x;
                acc[2 * q + 1] += f.y;
            }
        }
    }
    #pragma unroll
    for (int k = 0; k < 8; k++) {
        acc[k] += __shfl_xor_sync(0xffffffffu, acc[k], 8);
        acc[k] += __shfl_xor_sync(0xffffffffu, acc[k], 16);
    }
    {
        uint4 v = G4[(size_t)node * 8 + sub];
        const __half2* h = (const __half2*)&v;
        #pragma unroll
        for (int q = 0; q < 4; q++) {
            float2 f = __half22float2(h[q]);
            acc[2 * q]     += f.x;
            acc[2 * q + 1] += f.y;
        }
    }
    if (lane < 8) {
        float sc = g_dinv[node];
        float o[8];
        #pragma unroll
        for (int k = 0; k < 8; k++) {
            o[k] = acc[k] * sc + bias[lane * 8 + k];
            if (RELU) o[k] = (o[k] >= 0.f) ? o[k] : 0.01f * o[k];
        }
        float* dst = out + (size_t)node * 64 + lane * 8;
        *(float4*)(dst)     = make_float4(o[0], o[1], o[2], o[3]);
        *(float4*)(dst + 4) = make_float4(o[4], o[5], o[6], o[7]);
        // fp16 copy for the next GEMM
        __half2 hh[4] = { __floats2half2_rn(o[0], o[1]), __floats2half2_rn(o[2], o[3]),
                          __floats2half2_rn(o[4], o[5]), __floats2half2_rn(o[6], o[7]) };
        *(uint4*)&g_Hh[(size_t)node * 64 + lane * 8] = *(const uint4*)hh;
    }
}

// D=32: warp-per-node, 8 edges/iter. Sentinel remapped to the zero tail row.
template <bool RELU>
__global__ void k_agg32(const float* __restrict__ bias, float* __restrict__ out, int N) {
    int gid  = blockIdx.x * blockDim.x + threadIdx.x;
    int node = gid >> 5;
    int lane = gid & 31;
    if (node >= N) return;

    const uint4* __restrict__ G4 = (const uint4*)g_Gh;  // row = 4 granules
    int sub = lane & 3;
    int grp = lane >> 2;
    int beg = g_offs[node];
    int end = g_offs[node + 1];

    float acc[8];
    #pragma unroll
    for (int k = 0; k < 8; k++) acc[k] = 0.f;

    for (int e0 = beg; e0 < end; e0 += 32) {
        int idx = e0 + lane;
        int sl  = (idx < end) ? g_csrc[idx] : NMAX;
        int cnt = min(32, end - e0);          // multiple of 8
        for (int j = 0; j < cnt; j += 8) {
            int s = __shfl_sync(0xffffffffu, sl, j + grp);
            size_t rb = (s == NMAX) ? ((size_t)NMAX * 8) : ((size_t)s * 4);
            uint4 v = G4[rb + sub];
            const __half2* h = (const __half2*)&v;
            #pragma unroll
            for (int q = 0; q < 4; q++) {
                float2 f = __half22float2(h[q]);
                acc[2 * q]     += f.x;
                acc[2 * q + 1] += f.y;
            }
        }
    }
    #pragma unroll
    for (int k = 0; k < 8; k++) {
        acc[k] += __shfl_xor_sync(0xffffffffu, acc[k], 4);
        acc[k] += __shfl_xor_sync(0xffffffffu, acc[k], 8);
        acc[k] += __shfl_xor_sync(0xffffffffu, acc[k], 16);
    }
    {
        uint4 v = G4[(size_t)node * 4 + sub];
        const __half2* h = (const __half2*)&v;
        #pragma unroll
        for (int q = 0; q < 4; q++) {
            float2 f = __half22float2(h[q]);
            acc[2 * q]     += f.x;
            acc[2 * q + 1] += f.y;
        }
    }
    if (lane < 4) {
        float sc = g_dinv[node];
        float o[8];
        #pragma unroll
        for (int k = 0; k < 8; k++) {
            o[k] = acc[k] * sc + bias[lane * 8 + k];
            if (RELU) o[k] = (o[k] >= 0.f) ? o[k] : 0.01f * o[k];
        }
        float* dst = out + (size_t)node * 32 + lane * 8;
        *(float4*)(dst)     = make_float4(o[0], o[1], o[2], o[3]);
        *(float4*)(dst + 4) = make_float4(o[4], o[5], o[6], o[7]);
    }
}

// ---------------------------------------------------------------- launch
extern "C" void kernel_launch(void* const* d_in, const int* in_sizes, int n_in,
                              void* d_out, int out_size) {
    const float* x  = (const float*)d_in[0];
    const void*  ei = d_in[1];
    const float* W1 = (const float*)d_in[2];
    const float* b1 = (const float*)d_in[3];
    const float* W2 = (const float*)d_in[4];
    const float* b2 = (const float*)d_in[5];
    const float* W3 = (const float*)d_in[6];
    const float* b3 = (const float*)d_in[7];
    float* out = (float*)d_out;

    int N = in_sizes[0] / 64;
    int E = in_sizes[1] / 2;

    float* emb1 = out;
    float* emb2 = out + (size_t)N * 64;
    float* emb3 = out + (size_t)N * 128;

    int nblk = (N + SCAN_TILE - 1) / SCAN_TILE;
    int gemm_blocks = (N + 127) / 128;
    int agg_blocks = (N * 32 + 255) / 256;
    int cnt_threads = (E + 1) / 2 > N * 8 ? (E + 1) / 2 : N * 8;
    int cnt_blocks = (cnt_threads + 255) / 256;
    int edge_blocks = ((E + 1) / 2 + 255) / 256;

    // (1) fused convert + degree count
    k_count<<<cnt_blocks, 256>>>(ei, x, E, N);
    // (2) block sums + one-time W transpose/convert
    k_part<<<nblk, SCAN_TILE>>>(N, W1, W2, W3);
    k_offs<<<nblk, SCAN_TILE>>>(N);
    // (4) gemm1 — ncu capture slot: verify hoisted-W theory
    k_hgemm<64><<<gemm_blocks, 256>>>(0, N);
    k_fill<<<edge_blocks, 256>>>(ei, E, N);
    k_agg64<true><<<agg_blocks, 256>>>(b1, emb1, N);
    k_hgemm<64><<<gemm_blocks, 256>>>(1, N);
    k_agg64<true><<<agg_blocks, 256>>>(b2, emb2, N);
    k_hgemm<32><<<gemm_blocks, 256>>>(2, N);
    k_agg32<false><<<agg_blocks, 256>>>(b3, emb3, N);
}

// round 16
// speedup vs baseline: 1.0136x; 1.0130x over previous
#include <cuda_runtime.h>
#include <cuda_fp16.h>

// ===========================================================================
// GCN: 3 layers, pull-based padded-CSR aggregation, no float atomics.
//   out_i = leakyrelu( dinv_i * ( sum_{e: dst=i} g[src_e] + g[i] ) + b )
//   with g = fp16( (h @ W) * dinv )  (row-scaled in GEMM epilogue)
//
// R2: multi-block scan. R4: fp16 gather table. R5: padded 4/8-edge agg.
// R6: HMMA GEMM. R10: agg64 2-edge unroll. R13: W transpose hoisted (win).
// R16: k_fill and gemm1 are independent -> merged into ONE kernel with a
//      block-range split, overlapping the two largest independent pieces.
// ===========================================================================

#define NMAX 100000
#define EMAX 1600000
#define PADMAX (EMAX + 8 * NMAX)
#define SCAN_TILE 1024
#define NBLK ((NMAX + SCAN_TILE - 1) / SCAN_TILE)   // 98
#define WS 72   // padded stride of transposed W (halves)

__device__ int    g_deg[NMAX];                   // .bss zero; re-zeroed by k_offs
__device__ float  g_dinv[NMAX];
__device__ int    g_offs[NMAX + 1];              // padded CSR offsets
__device__ int    g_cur[NMAX];
__device__ int    g_csrc[PADMAX];
__device__ int    g_bsum[NBLK];
__device__ __align__(16) __half g_Gh[(size_t)(NMAX + 1) * 64]; // gather table (+ zero row)
__device__ __align__(16) __half g_Hh[(size_t)NMAX * 64];       // fp16 layer input
__device__ __align__(16) __half g_Wt[3][64 * WS];              // fp16 transposed weights

// per-warp dtype probe: int64 entries < 2^31 have zero high words; for int32
// data those words are random node ids -> 16 zeros is impossible.
__device__ __forceinline__ int probe_is64(const unsigned* w, int lane) {
    unsigned hw = w[2 * (lane & 15) + 1];
    return __ballot_sync(0xffffffffu, hw == 0u) == 0xffffffffu;
}

// ---------------------------------------------------------------- CSR build
// Fused: degree count (2 edges/thread) + x fp32->fp16 convert (8 vals/thread).
__global__ void k_count(const void* __restrict__ ei, const float* __restrict__ x,
                        int E, int N) {
    int lane = threadIdx.x & 31;
    int is64 = probe_is64((const unsigned*)ei, lane);
    int t = blockIdx.x * blockDim.x + threadIdx.x;

    int nv = N * 8;                 // uint4 granules of fp16 output
    if (t < nv) {
        const float4* xf = (const float4*)x;
        float4 a = xf[(size_t)t * 2];
        float4 b = xf[(size_t)t * 2 + 1];
        __half2 h[4] = { __floats2half2_rn(a.x, a.y), __floats2half2_rn(a.z, a.w),
                         __floats2half2_rn(b.x, b.y), __floats2half2_rn(b.z, b.w) };
        *(uint4*)&g_Hh[(size_t)t * 8] = *(const uint4*)h;
    }

    int e0 = t * 2;
    if (e0 >= E) return;
    int d0, d1;
    if (is64) {
        longlong2 v = ((const longlong2*)ei)[((size_t)E + e0) >> 1];
        d0 = (int)v.x; d1 = (int)v.y;
    } else {
        int2 v = ((const int2*)ei)[((size_t)E + e0) >> 1];
        d0 = v.x; d1 = v.y;
    }
    if ((unsigned)d0 < (unsigned)N) atomicAdd(&g_deg[d0], 1);
    if (e0 + 1 < E && (unsigned)d1 < (unsigned)N) atomicAdd(&g_deg[d1], 1);
}

// per-block sums of PADDED degrees; also one-time W transpose/convert.
__global__ void k_part(int N, const float* __restrict__ W1,
                       const float* __restrict__ W2, const float* __restrict__ W3) {
    int t = blockIdx.x * SCAN_TILE + threadIdx.x;
    if (t < 2 * 4096 + 2048) {
        const float* W;
        int layer, idx, dout;
        if (t < 4096)       { layer = 0; idx = t;        W = W1; dout = 64; }
        else if (t < 8192)  { layer = 1; idx = t - 4096; W = W2; dout = 64; }
        else                { layer = 2; idx = t - 8192; W = W3; dout = 32; }
        int k = idx / dout, n = idx % dout;
        g_Wt[layer][n * WS + k] = __float2half_rn(W[idx]);
    }

    int i = t;
    int d  = (i < N) ? g_deg[i] : 0;
    int pd = (d + 7) & ~7;
    int lane = threadIdx.x & 31, wid = threadIdx.x >> 5;
    #pragma unroll
    for (int o = 16; o > 0; o >>= 1) pd += __shfl_down_sync(0xffffffffu, pd, o);
    __shared__ int ws[32];
    if (lane == 0) ws[wid] = pd;
    __syncthreads();
    if (wid == 0) {
        int v = ws[lane];
        #pragma unroll
        for (int o = 16; o > 0; o >>= 1) v += __shfl_down_sync(0xffffffffu, v, o);
        if (lane == 0) g_bsum[blockIdx.x] = v;
    }
}

// fused: scan of block sums + block-wide scan of padded degrees ->
// offs/cur/dinv, sentinel pad fill, and re-zero g_deg for the next call.
__global__ void k_offs(int N) {
    __shared__ int sb[128];
    __shared__ int ws[32];
    int t = threadIdx.x;

    if (t < 128) {
        int v = (t < NBLK) ? g_bsum[t] : 0;
        int lane = t & 31, w = t >> 5;
        int s = v;
        #pragma unroll
        for (int o = 1; o < 32; o <<= 1) {
            int u = __shfl_up_sync(0xffffffffu, s, o);
            if (lane >= o) s += u;
        }
        if (lane == 31) ws[w] = s;
        sb[t] = s;
    }
    __syncthreads();
    if (t < 128) {
        int w = t >> 5;
        int add = 0;
        for (int q = 0; q < w; q++) add += ws[q];
        sb[t] += add;
    }
    __syncthreads();
    int blockpre = (blockIdx.x == 0) ? 0 : sb[blockIdx.x - 1];
    __syncthreads();  // ws reused below

    int i = blockIdx.x * SCAN_TILE + t;
    int d  = (i < N) ? g_deg[i] : 0;
    int pd = (d + 7) & ~7;
    int lane = t & 31, wid = t >> 5;
    int v = pd;
    #pragma unroll
    for (int o = 1; o < 32; o <<= 1) {
        int u = __shfl_up_sync(0xffffffffu, v, o);
        if (lane >= o) v += u;
    }
    if (lane == 31) ws[wid] = v;
    __syncthreads();
    if (wid == 0) {
        int w = ws[lane];
        #pragma unroll
        for (int o = 1; o < 32; o <<= 1) {
            int u = __shfl_up_sync(0xffffffffu, w, o);
            if (lane >= o) w += u;
        }
        ws[lane] = w;
    }
    __syncthreads();
    int incl = v + ((wid > 0) ? ws[wid - 1] : 0);
    int excl = incl - pd + blockpre;
    if (i < N) {
        g_offs[i] = excl;
        g_cur[i]  = excl;
        g_dinv[i] = rsqrtf((float)(d + 1));     // +1 self loop (real degree)
        for (int p = excl + d; p < excl + pd; p++) g_csrc[p] = NMAX;  // sentinel
        g_deg[i] = 0;                            // ready for next replay
        if (i == N - 1) g_offs[N] = excl + pd;
    }
}

// ---------------------------------------------------------------- bodies
__device__ __forceinline__ void fill_body(const void* __restrict__ ei,
                                          int E, int N, int bx) {
    int lane = threadIdx.x & 31;
    int is64 = probe_is64((const unsigned*)ei, lane);
    int t = bx * 256 + threadIdx.x;
    int e0 = t * 2;
    if (e0 >= E) return;
    int s0, s1, d0, d1;
    if (is64) {
        longlong2 sv = ((const longlong2*)ei)[(size_t)e0 >> 1];
        longlong2 dv = ((const longlong2*)ei)[((size_t)E + e0) >> 1];
        s0 = (int)sv.x; s1 = (int)sv.y;
        d0 = (int)dv.x; d1 = (int)dv.y;
    } else {
        int2 sv = ((const int2*)ei)[(size_t)e0 >> 1];
        int2 dv = ((const int2*)ei)[((size_t)E + e0) >> 1];
        s0 = sv.x; s1 = sv.y;
        d0 = dv.x; d1 = dv.y;
    }
    if ((unsigned)d0 < (unsigned)N) {
        int pos = atomicAdd(&g_cur[d0], 1);
        g_csrc[pos] = ((unsigned)s0 < (unsigned)N) ? s0 : 0;
    }
    if (e0 + 1 < E && (unsigned)d1 < (unsigned)N) {
        int pos = atomicAdd(&g_cur[d1], 1);
        g_csrc[pos] = ((unsigned)s1 < (unsigned)N) ? s1 : 0;
    }
}

__device__ __forceinline__ void mma16816(float c[4], unsigned a0, unsigned a1,
                                         unsigned a2, unsigned a3,
                                         unsigned b0, unsigned b1) {
    asm volatile(
        "mma.sync.aligned.m16n8k16.row.col.f32.f16.f16.f32 "
        "{%0,%1,%2,%3}, {%4,%5,%6,%7}, {%8,%9}, {%0,%1,%2,%3};"
        : "+f"(c[0]), "+f"(c[1]), "+f"(c[2]), "+f"(c[3])
        : "r"(a0), "r"(a1), "r"(a2), "r"(a3), "r"(b0), "r"(b1));
}

__device__ __forceinline__ void ldsm_x4(unsigned& r0, unsigned& r1,
                                        unsigned& r2, unsigned& r3,
                                        unsigned addr) {
    asm volatile(
        "ldmatrix.sync.aligned.m8n8.x4.shared.b16 {%0,%1,%2,%3}, [%4];"
        : "=r"(r0), "=r"(r1), "=r"(r2), "=r"(r3) : "r"(addr));
}

// g_Gh = fp16( (g_Hh @ W) * dinv[row] ).  W from precomputed g_Wt.
// 256 threads / 8 warps, tile 128 rows x DOUT, K=64. All staging uint4.
template <int DOUT>
__device__ __forceinline__ void gemm_body(int layer, int N, int bx,
                                          __half* sX, __half* sWt) {
    constexpr int S = WS;
    int tid = threadIdx.x, lane = tid & 31, w = tid >> 5;
    int rowBase = bx * 128;

    {
        const uint4* src = (const uint4*)g_Wt[layer];
        uint4* dst = (uint4*)sWt;
        #pragma unroll
        for (int i = tid; i < DOUT * (S / 8); i += 256) dst[i] = src[i];
    }
    const uint4* Hv = (const uint4*)g_Hh;
    #pragma unroll
    for (int i = 0; i < 4; i++) {
        int idx = tid + i * 256;            // uint4 index within 128x8
        int r = idx >> 3, c8 = idx & 7;
        int grow = rowBase + r;
        uint4 v = (grow < N) ? Hv[(size_t)grow * 8 + c8]
                             : make_uint4(0u, 0u, 0u, 0u);
        *(uint4*)&sX[r * S + c8 * 8] = v;
    }
    __syncthreads();

    constexpr int NT = DOUT / 8;
    float acc[NT][4];
    #pragma unroll
    for (int nt = 0; nt < NT; nt++)
        #pragma unroll
        for (int q = 0; q < 4; q++) acc[nt][q] = 0.f;

    unsigned xs  = (unsigned)__cvta_generic_to_shared(sX);
    unsigned wsb = (unsigned)__cvta_generic_to_shared(sWt);
    int arow  = w * 16 + (lane & 15);
    int acol8 = (lane >> 4) * 8;
    int bn  = ((lane >> 4) << 3) | (lane & 7);
    int bk8 = ((lane >> 3) & 1) << 3;

    #pragma unroll
    for (int kt = 0; kt < 4; kt++) {
        int k0 = kt * 16;
        unsigned a0, a1, a2, a3;
        ldsm_x4(a0, a1, a2, a3, xs + (arow * S + k0 + acol8) * 2);
        #pragma unroll
        for (int nt2 = 0; nt2 < NT / 2; nt2++) {
            unsigned b00, b01, b10, b11;
            ldsm_x4(b00, b01, b10, b11,
                    wsb + ((nt2 * 16 + bn) * S + k0 + bk8) * 2);
            mma16816(acc[nt2 * 2],     a0, a1, a2, a3, b00, b01);
            mma16816(acc[nt2 * 2 + 1], a0, a1, a2, a3, b10, b11);
        }
    }

    int g = lane >> 2, tg = lane & 3;
    int gr0 = rowBase + w * 16 + g, gr1 = gr0 + 8;
    bool ok0 = gr0 < N, ok1 = gr1 < N;
    float s0 = ok0 ? g_dinv[gr0] : 0.f;
    float s1 = ok1 ? g_dinv[gr1] : 0.f;
    __half2* Gh2 = (__half2*)g_Gh;
    #pragma unroll
    for (int nt = 0; nt < NT; nt++) {
        int col = nt * 8 + tg * 2;
        if (ok0)
            Gh2[((size_t)gr0 * DOUT + col) >> 1] =
                __floats2half2_rn(acc[nt][0] * s0, acc[nt][1] * s0);
        if (ok1)
            Gh2[((size_t)gr1 * DOUT + col) >> 1] =
                __floats2half2_rn(acc[nt][2] * s1, acc[nt][3] * s1);
    }
}

// standalone GEMM kernels (layers 2, 3)
template <int DOUT>
__global__ void k_hgemm(int layer, int N) {
    __shared__ __align__(16) __half sX[128 * WS];
    __shared__ __align__(16) __half sWt[DOUT * WS];
    gemm_body<DOUT>(layer, N, blockIdx.x, sX, sWt);
}

// merged: gemm layer-1 (blocks [0, gemmBlocks)) + edge fill (rest).
// The two are independent; overlapping them hides the fill latency.
__global__ void k_gfill(const void* __restrict__ ei, int E, int N, int gemmBlocks) {
    __shared__ __align__(16) __half sX[128 * WS];
    __shared__ __align__(16) __half sWt[64 * WS];
    if ((int)blockIdx.x < gemmBlocks) {
        gemm_body<64>(0, N, blockIdx.x, sX, sWt);
    } else {
        fill_body(ei, E, N, blockIdx.x - gemmBlocks);
    }
}

// ---------------------------------------------------------------- aggregate
// D=64: warp-per-node, 8 edges/iter, fp16 pair-add then fp32 accumulate.
// Also emits the fp16 copy of the layer output (next GEMM's input).
template <bool RELU>
__global__ void k_agg64(const float* __restrict__ bias, float* __restrict__ out, int N) {
    int gid  = blockIdx.x * blockDim.x + threadIdx.x;
    int node = gid >> 5;
    int lane = gid & 31;
    if (node >= N) return;

    const uint4* __restrict__ G4 = (const uint4*)g_Gh;  // row = 8 granules
    int sub = lane & 7;
    int grp = lane >> 3;
    int beg = g_offs[node];
    int end = g_offs[node + 1];

    float acc[8];
    #pragma unroll
    for (int k = 0; k < 8; k++) acc[k] = 0.f;

    for (int e0 = beg; e0 < end; e0 += 32) {
        int idx = e0 + lane;
        int sl  = (idx < end) ? g_csrc[idx] : NMAX;
        int cnt = min(32, end - e0);          // multiple of 8
        for (int j = 0; j < cnt; j += 8) {
            int s1 = __shfl_sync(0xffffffffu, sl, j + grp);
            int s2 = __shfl_sync(0xffffffffu, sl, j + 4 + grp);
            uint4 v1 = G4[(size_t)s1 * 8 + sub];
            uint4 v2 = G4[(size_t)s2 * 8 + sub];
            const __half2* h1 = (const __half2*)&v1;
            const __half2* h2 = (const __half2*)&v2;
            #pragma unroll
            for (int q = 0; q < 4; q++) {
                float2 f = __half22float2(__hadd2(h1[q], h2[q]));
                acc[2 * q]     += f.x;
                acc[2 * q + 1] += f.y;
            }
        }
    }
    #pragma unroll
    for (int k = 0; k < 8; k++) {
        acc[k] += __shfl_xor_sync(0xffffffffu, acc[k], 8);
        acc[k] += __shfl_xor_sync(0xffffffffu, acc[k], 16);
    }
    {
        uint4 v = G4[(size_t)node * 8 + sub];
        const __half2* h = (const __half2*)&v;
        #pragma unroll
        for (int q = 0; q < 4; q++) {
            float2 f = __half22float2(h[q]);
            acc[2 * q]     += f.x;
            acc[2 * q + 1] += f.y;
        }
    }
    if (lane < 8) {
        float sc = g_dinv[node];
        float o[8];
        #pragma unroll
        for (int k = 0; k < 8; k++) {
            o[k] = acc[k] * sc + bias[lane * 8 + k];
            if (RELU) o[k] = (o[k] >= 0.f) ? o[k] : 0.01f * o[k];
        }
        float* dst = out + (size_t)node * 64 + lane * 8;
        *(float4*)(dst)     = make_float4(o[0], o[1], o[2], o[3]);
        *(float4*)(dst + 4) = make_float4(o[4], o[5], o[6], o[7]);
        __half2 hh[4] = { __floats2half2_rn(o[0], o[1]), __floats2half2_rn(o[2], o[3]),
                          __floats2half2_rn(o[4], o[5]), __floats2half2_rn(o[6], o[7]) };
        *(uint4*)&g_Hh[(size_t)node * 64 + lane * 8] = *(const uint4*)hh;
    }
}

// D=32: warp-per-node, 8 edges/iter. Sentinel remapped to the zero tail row.
template <bool RELU>
__global__ void k_agg32(const float* __restrict__ bias, float* __restrict__ out, int N) {
    int gid  = blockIdx.x * blockDim.x + threadIdx.x;
    int node = gid >> 5;
    int lane = gid & 31;
    if (node >= N) return;

    const uint4* __restrict__ G4 = (const uint4*)g_Gh;  // row = 4 granules
    int sub = lane & 3;
    int grp = lane >> 2;
    int beg = g_offs[node];
    int end = g_offs[node + 1];

    float acc[8];
    #pragma unroll
    for (int k = 0; k < 8; k++) acc[k] = 0.f;

    for (int e0 = beg; e0 < end; e0 += 32) {
        int idx = e0 + lane;
        int sl  = (idx < end) ? g_csrc[idx] : NMAX;
        int cnt = min(32, end - e0);          // multiple of 8
        for (int j = 0; j < cnt; j += 8) {
            int s = __shfl_sync(0xffffffffu, sl, j + grp);
            size_t rb = (s == NMAX) ? ((size_t)NMAX * 8) : ((size_t)s * 4);
            uint4 v = G4[rb + sub];
            const __half2* h = (const __half2*)&v;
            #pragma unroll
            for (int q = 0; q < 4; q++) {
                float2 f = __half22float2(h[q]);
                acc[2 * q]     += f.x;
                acc[2 * q + 1] += f.y;
            }
        }
    }
    #pragma unroll
    for (int k = 0; k < 8; k++) {
        acc[k] += __shfl_xor_sync(0xffffffffu, acc[k], 4);
        acc[k] += __shfl_xor_sync(0xffffffffu, acc[k], 8);
        acc[k] += __shfl_xor_sync(0xffffffffu, acc[k], 16);
    }
    {
        uint4 v = G4[(size_t)node * 4 + sub];
        const __half2* h = (const __half2*)&v;
        #pragma unroll
        for (int q = 0; q < 4; q++) {
            float2 f = __half22float2(h[q]);
            acc[2 * q]     += f.x;
            acc[2 * q + 1] += f.y;
        }
    }
    if (lane < 4) {
        float sc = g_dinv[node];
        float o[8];
        #pragma unroll
        for (int k = 0; k < 8; k++) {
            o[k] = acc[k] * sc + bias[lane * 8 + k];
            if (RELU) o[k] = (o[k] >= 0.f) ? o[k] : 0.01f * o[k];
        }
        float* dst = out + (size_t)node * 32 + lane * 8;
        *(float4*)(dst)     = make_float4(o[0], o[1], o[2], o[3]);
        *(float4*)(dst + 4) = make_float4(o[4], o[5], o[6], o[7]);
    }
}

// ---------------------------------------------------------------- launch
extern "C" void kernel_launch(void* const* d_in, const int* in_sizes, int n_in,
                              void* d_out, int out_size) {
    const float* x  = (const float*)d_in[0];
    const void*  ei = d_in[1];
    const float* W1 = (const float*)d_in[2];
    const float* b1 = (const float*)d_in[3];
    const float* W2 = (const float*)d_in[4];
    const float* b2 = (const float*)d_in[5];
    const float* W3 = (const float*)d_in[6];
    const float* b3 = (const float*)d_in[7];
    float* out = (float*)d_out;

    int N = in_sizes[0] / 64;
    int E = in_sizes[1] / 2;

    float* emb1 = out;
    float* emb2 = out + (size_t)N * 64;
    float* emb3 = out + (size_t)N * 128;

    int nblk = (N + SCAN_TILE - 1) / SCAN_TILE;
    int gemm_blocks = (N + 127) / 128;
    int agg_blocks = (N * 32 + 255) / 256;
    int cnt_threads = (E + 1) / 2 > N * 8 ? (E + 1) / 2 : N * 8;
    int cnt_blocks = (cnt_threads + 255) / 256;
    int edge_blocks = ((E + 1) / 2 + 255) / 256;

    // (1) fused convert + degree count
    k_count<<<cnt_blocks, 256>>>(ei, x, E, N);
    // (2) block sums + one-time W transpose/convert
    k_part<<<nblk, SCAN_TILE>>>(N, W1, W2, W3);
    k_offs<<<nblk, SCAN_TILE>>>(N);
    // (4) merged gemm1 + fill — ncu capture slot
    k_gfill<<<gemm_blocks + edge_blocks, 256>>>(ei, E, N, gemm_blocks);
    k_agg64<true><<<agg_blocks, 256>>>(b1, emb1, N);
    k_hgemm<64><<<gemm_blocks, 256>>>(1, N);
    k_agg64<true><<<agg_blocks, 256>>>(b2, emb2, N);
    k_hgemm<32><<<gemm_blocks, 256>>>(2, N);
    k_agg32<false><<<agg_blocks, 256>>>(b3, emb3, N);
}